// round 2
// baseline (speedup 1.0000x reference)
#include <cuda_runtime.h>
#include <math.h>

#define BB 64
#define TT 2048
#define DD 256
#define EPSV 1e-7f

// Scratch (device globals — no allocations allowed)
__device__ float g_ascore[BB * TT];   // exp(score)*mask per token
__device__ float g_denom[BB];         // sum over T + EPS

// ---------------------------------------------------------------------------
// K1: fused  scores = exp( uw . tanh(x @ W + b) ) * mask
// Tile: 64 tokens x 256 outputs, K=256 in slabs of 16. 256 threads,
// each thread computes a 4x16 register tile. Epilogue fuses tanh/uw/reduce/exp.
// ---------------------------------------------------------------------------
__global__ __launch_bounds__(256, 2) void score_kernel(
    const float* __restrict__ x, const float* __restrict__ W,
    const float* __restrict__ bias, const float* __restrict__ uw,
    const int* __restrict__ mask)
{
    __shared__ float xs[16][64 + 4];   // [k][m], padded
    __shared__ float ws[16][256];      // [k][e]
    __shared__ float red[64][17];      // token x tn partials, padded

    const int tid = threadIdx.x;
    const int tm = tid >> 4;    // 0..15  (token group: 4 tokens)
    const int tn = tid & 15;    // 0..15  (e group: 16 outputs)
    const int tile0 = blockIdx.x * 64;  // first global token of tile

    float acc[4][16];
    #pragma unroll
    for (int i = 0; i < 4; i++)
        #pragma unroll
        for (int j = 0; j < 16; j++) acc[i][j] = 0.0f;

    for (int k0 = 0; k0 < DD; k0 += 16) {
        // load x tile: 64 tokens x 16 k — one float4 per thread, coalesced on k
        {
            const int m  = tid >> 2;          // 0..63
            const int kq = (tid & 3) * 4;     // 0,4,8,12
            const float4 v = *reinterpret_cast<const float4*>(
                &x[(size_t)(tile0 + m) * DD + k0 + kq]);
            xs[kq + 0][m] = v.x; xs[kq + 1][m] = v.y;
            xs[kq + 2][m] = v.z; xs[kq + 3][m] = v.w;
        }
        // load W tile: 16 k x 256 e — 4 float4 per thread, coalesced on e
        {
            const int k  = tid >> 4;          // 0..15
            const int e0 = (tid & 15) * 16;   // 0..240
            const float4* src = reinterpret_cast<const float4*>(
                &W[(size_t)(k0 + k) * DD + e0]);
            float4* dst = reinterpret_cast<float4*>(&ws[k][e0]);
            #pragma unroll
            for (int q = 0; q < 4; q++) dst[q] = src[q];
        }
        __syncthreads();

        #pragma unroll
        for (int k = 0; k < 16; k++) {
            float av[4];
            #pragma unroll
            for (int i = 0; i < 4; i++) av[i] = xs[k][tm * 4 + i];
            float bv[16];
            #pragma unroll
            for (int j = 0; j < 4; j++) {
                const float4 w4 = *reinterpret_cast<const float4*>(&ws[k][tn * 16 + j * 4]);
                bv[j * 4 + 0] = w4.x; bv[j * 4 + 1] = w4.y;
                bv[j * 4 + 2] = w4.z; bv[j * 4 + 3] = w4.w;
            }
            #pragma unroll
            for (int i = 0; i < 4; i++)
                #pragma unroll
                for (int j = 0; j < 16; j++)
                    acc[i][j] = fmaf(av[i], bv[j], acc[i][j]);
        }
        __syncthreads();
    }

    // epilogue: sum_j tanh(acc + b[e]) * uw[e] for the 16 e's this thread owns
    #pragma unroll
    for (int i = 0; i < 4; i++) {
        float s = 0.0f;
        #pragma unroll
        for (int j = 0; j < 16; j++) {
            const int e = tn * 16 + j;
            s += tanhf(acc[i][j] + __ldg(&bias[e])) * __ldg(&uw[e]);
        }
        red[tm * 4 + i][tn] = s;
    }
    __syncthreads();

    if (tid < 64) {
        float s = 0.0f;
        #pragma unroll
        for (int j = 0; j < 16; j++) s += red[tid][j];
        const int gi = tile0 + tid;
        g_ascore[gi] = expf(s) * (float)__ldg(&mask[gi]);
    }
}

// ---------------------------------------------------------------------------
// K2: per-batch denom = sum_t a_t + EPS
// ---------------------------------------------------------------------------
__global__ __launch_bounds__(256) void denom_kernel()
{
    __shared__ float sm[256];
    const int b = blockIdx.x;
    float s = 0.0f;
    for (int t = threadIdx.x; t < TT; t += 256) s += g_ascore[b * TT + t];
    sm[threadIdx.x] = s;
    __syncthreads();
    for (int off = 128; off > 0; off >>= 1) {
        if (threadIdx.x < off) sm[threadIdx.x] += sm[threadIdx.x + off];
        __syncthreads();
    }
    if (threadIdx.x == 0) g_denom[b] = sm[0] + EPSV;
}

// ---------------------------------------------------------------------------
// K3: zero output (harness poisons it)
// ---------------------------------------------------------------------------
__global__ void zero_kernel(float* __restrict__ out)
{
    out[blockIdx.x * blockDim.x + threadIdx.x] = 0.0f;
}

// ---------------------------------------------------------------------------
// K4: out[b,d] = sum_t x[b,t,d] * a_t / denom[b]   (T split 16-way, atomics)
// ---------------------------------------------------------------------------
__global__ __launch_bounds__(256) void wsum_kernel(
    const float* __restrict__ x, float* __restrict__ out)
{
    const int b  = blockIdx.y;
    const int t0 = blockIdx.x * (TT / 16);     // 128 tokens per block
    const int d  = threadIdx.x;

    __shared__ float asm_[TT / 16];
    for (int t = threadIdx.x; t < TT / 16; t += 256)
        asm_[t] = g_ascore[b * TT + t0 + t];
    __syncthreads();

    const float inv = 1.0f / g_denom[b];
    float acc = 0.0f;
    const float* xp = &x[((size_t)b * TT + t0) * DD + d];
    #pragma unroll 8
    for (int t = 0; t < TT / 16; t++)
        acc = fmaf(xp[(size_t)t * DD], asm_[t], acc);

    atomicAdd(&out[b * DD + d], acc * inv);
}

// ---------------------------------------------------------------------------
extern "C" void kernel_launch(void* const* d_in, const int* in_sizes, int n_in,
                              void* d_out, int out_size)
{
    const float* x    = (const float*)d_in[0];
    const float* W    = (const float*)d_in[1];
    const float* bias = (const float*)d_in[2];
    const float* uw   = (const float*)d_in[3];
    const int*   mask = (const int*)d_in[4];
    float* out = (float*)d_out;

    score_kernel<<<(BB * TT) / 64, 256>>>(x, W, bias, uw, mask);
    denom_kernel<<<BB, 256>>>();
    zero_kernel<<<(BB * DD) / 256, 256>>>(out);
    dim3 g(16, BB);
    wsum_kernel<<<g, 256>>>(x, out);
}

// round 3
// speedup vs baseline: 3.2986x; 3.2986x over previous
#include <cuda_runtime.h>
#include <cuda_bf16.h>
#include <math.h>

#define BB 64
#define TT 2048
#define DD 256
#define EPSV 1e-7f

// Scratch (device globals — no allocations allowed)
__device__ float g_ascore[BB * TT];   // exp(score)*mask per token
__device__ float g_denom[BB];         // sum over T + EPS

// pack two floats as bf16 pair (a -> low 16, b -> high 16)
__device__ __forceinline__ unsigned pack_bf16(float a, float b) {
    __nv_bfloat162 h = __floats2bfloat162_rn(a, b);
    return *reinterpret_cast<unsigned*>(&h);
}

__device__ __forceinline__ void mma_bf16(float c[4], const unsigned a[4], const unsigned b[2]) {
    asm volatile(
        "mma.sync.aligned.m16n8k16.row.col.f32.bf16.bf16.f32 "
        "{%0,%1,%2,%3}, {%4,%5,%6,%7}, {%8,%9}, {%0,%1,%2,%3};\n"
        : "+f"(c[0]), "+f"(c[1]), "+f"(c[2]), "+f"(c[3])
        : "r"(a[0]), "r"(a[1]), "r"(a[2]), "r"(a[3]), "r"(b[0]), "r"(b[1]));
}

// ---------------------------------------------------------------------------
// K1: fused  scores = exp( uw . tanh(x @ W + b) ) * mask   via bf16x3 MMA
// Block: 256 thr (8 warps). Tile M=64 tokens x N=256 (full), K slab = 32.
// Warps split N (32 cols each): per warp 4 m-tiles(16) x 4 n-tiles(8).
// ---------------------------------------------------------------------------
__global__ __launch_bounds__(256, 2) void score_kernel(
    const float* __restrict__ x, const float* __restrict__ W,
    const float* __restrict__ bias, const float* __restrict__ uw,
    const int* __restrict__ mask)
{
    // packed bf16 pairs along k: [row][kpair]
    __shared__ unsigned xs_h[64][17],  xs_l[64][17];    // 8.5 KB
    __shared__ unsigned ws_h[256][17], ws_l[256][17];   // 34 KB
    __shared__ float sbias[256], suw[256];
    __shared__ float red[64][9];

    const int tid  = threadIdx.x;
    const int warp = tid >> 5;
    const int lane = tid & 31;
    const int gid  = lane >> 2;    // groupID 0..7
    const int tig  = lane & 3;     // thread-in-group
    const int n0   = warp * 32;    // this warp's e-column base
    const long tile0 = (long)blockIdx.x * 64;

    sbias[tid] = bias[tid];
    suw[tid]   = uw[tid];

    float acc[4][4][4];
    #pragma unroll
    for (int i = 0; i < 4; i++)
        #pragma unroll
        for (int j = 0; j < 4; j++)
            #pragma unroll
            for (int q = 0; q < 4; q++) acc[i][j][q] = 0.0f;

    for (int k0 = 0; k0 < DD; k0 += 32) {
        __syncthreads();   // previous slab fully consumed (also orders sbias)

        // ---- stage x slab: 64 rows x 32 k, split into bf16 hi/lo pairs ----
        #pragma unroll
        for (int r = 0; r < 2; r++) {
            const int idx = tid + r * 256;
            const int row = idx >> 3;
            const int kq  = (idx & 7) * 4;
            const float4 v = *reinterpret_cast<const float4*>(
                &x[(tile0 + row) * DD + k0 + kq]);
            const float hx = __bfloat162float(__float2bfloat16_rn(v.x));
            const float hy = __bfloat162float(__float2bfloat16_rn(v.y));
            const float hz = __bfloat162float(__float2bfloat16_rn(v.z));
            const float hw = __bfloat162float(__float2bfloat16_rn(v.w));
            xs_h[row][kq/2 + 0] = pack_bf16(hx, hy);
            xs_h[row][kq/2 + 1] = pack_bf16(hz, hw);
            xs_l[row][kq/2 + 0] = pack_bf16(v.x - hx, v.y - hy);
            xs_l[row][kq/2 + 1] = pack_bf16(v.z - hz, v.w - hw);
        }

        // ---- stage W slab: 32 k x 256 e, packed (k,k+1) per e ----
        {
            const int p  = tid >> 4;    // kpair 0..15
            const int eq = tid & 15;    // e group
            #pragma unroll
            for (int c = 0; c < 4; c++) {
                const int e = eq * 16 + c * 4;
                const float4 va = *reinterpret_cast<const float4*>(
                    &W[(size_t)(k0 + 2 * p) * DD + e]);
                const float4 vb = *reinterpret_cast<const float4*>(
                    &W[(size_t)(k0 + 2 * p + 1) * DD + e]);
                const float hax = __bfloat162float(__float2bfloat16_rn(va.x));
                const float hay = __bfloat162float(__float2bfloat16_rn(va.y));
                const float haz = __bfloat162float(__float2bfloat16_rn(va.z));
                const float haw = __bfloat162float(__float2bfloat16_rn(va.w));
                const float hbx = __bfloat162float(__float2bfloat16_rn(vb.x));
                const float hby = __bfloat162float(__float2bfloat16_rn(vb.y));
                const float hbz = __bfloat162float(__float2bfloat16_rn(vb.z));
                const float hbw = __bfloat162float(__float2bfloat16_rn(vb.w));
                ws_h[e + 0][p] = pack_bf16(hax, hbx);
                ws_h[e + 1][p] = pack_bf16(hay, hby);
                ws_h[e + 2][p] = pack_bf16(haz, hbz);
                ws_h[e + 3][p] = pack_bf16(haw, hbw);
                ws_l[e + 0][p] = pack_bf16(va.x - hax, vb.x - hbx);
                ws_l[e + 1][p] = pack_bf16(va.y - hay, vb.y - hby);
                ws_l[e + 2][p] = pack_bf16(va.z - haz, vb.z - hbz);
                ws_l[e + 3][p] = pack_bf16(va.w - haw, vb.w - hbw);
            }
        }
        __syncthreads();

        // ---- 2 k-steps of m16n8k16 per slab ----
        #pragma unroll
        for (int kk = 0; kk < 2; kk++) {
            const int kb = kk * 8;
            unsigned bh[4][2], bl[4][2];
            #pragma unroll
            for (int j = 0; j < 4; j++) {
                const int n = n0 + j * 8 + gid;
                bh[j][0] = ws_h[n][kb + tig];     bh[j][1] = ws_h[n][kb + tig + 4];
                bl[j][0] = ws_l[n][kb + tig];     bl[j][1] = ws_l[n][kb + tig + 4];
            }
            #pragma unroll
            for (int i = 0; i < 4; i++) {
                const int m = i * 16;
                unsigned ah[4], al[4];
                ah[0] = xs_h[m + gid    ][kb + tig];
                ah[1] = xs_h[m + gid + 8][kb + tig];
                ah[2] = xs_h[m + gid    ][kb + tig + 4];
                ah[3] = xs_h[m + gid + 8][kb + tig + 4];
                al[0] = xs_l[m + gid    ][kb + tig];
                al[1] = xs_l[m + gid + 8][kb + tig];
                al[2] = xs_l[m + gid    ][kb + tig + 4];
                al[3] = xs_l[m + gid + 8][kb + tig + 4];
                #pragma unroll
                for (int j = 0; j < 4; j++) {
                    mma_bf16(acc[i][j], ah, bh[j]);   // hi*hi
                    mma_bf16(acc[i][j], ah, bl[j]);   // hi*lo
                    mma_bf16(acc[i][j], al, bh[j]);   // lo*hi
                }
            }
        }
    }

    // ---- epilogue: per-row  sum_e tanh(v + b[e]) * uw[e] ----
    #pragma unroll
    for (int i = 0; i < 4; i++) {
        float s0 = 0.0f, s1 = 0.0f;
        #pragma unroll
        for (int j = 0; j < 4; j++) {
            const int e = n0 + j * 8 + tig * 2;
            const float b0 = sbias[e], b1 = sbias[e + 1];
            const float u0 = suw[e],   u1 = suw[e + 1];
            s0 += tanhf(acc[i][j][0] + b0) * u0 + tanhf(acc[i][j][1] + b1) * u1;
            s1 += tanhf(acc[i][j][2] + b0) * u0 + tanhf(acc[i][j][3] + b1) * u1;
        }
        s0 += __shfl_xor_sync(0xffffffffu, s0, 1);
        s0 += __shfl_xor_sync(0xffffffffu, s0, 2);
        s1 += __shfl_xor_sync(0xffffffffu, s1, 1);
        s1 += __shfl_xor_sync(0xffffffffu, s1, 2);
        if (tig == 0) {
            red[i * 16 + gid    ][warp] = s0;
            red[i * 16 + gid + 8][warp] = s1;
        }
    }
    __syncthreads();

    if (tid < 64) {
        float s = 0.0f;
        #pragma unroll
        for (int w = 0; w < 8; w++) s += red[tid][w];
        const long gi = tile0 + tid;
        g_ascore[gi] = expf(s) * (float)mask[gi];
    }
}

// ---------------------------------------------------------------------------
// K2: per-batch denom = sum_t a_t + EPS
// ---------------------------------------------------------------------------
__global__ __launch_bounds__(256) void denom_kernel()
{
    __shared__ float sm[256];
    const int b = blockIdx.x;
    float s = 0.0f;
    for (int t = threadIdx.x; t < TT; t += 256) s += g_ascore[b * TT + t];
    sm[threadIdx.x] = s;
    __syncthreads();
    for (int off = 128; off > 0; off >>= 1) {
        if (threadIdx.x < off) sm[threadIdx.x] += sm[threadIdx.x + off];
        __syncthreads();
    }
    if (threadIdx.x == 0) g_denom[b] = sm[0] + EPSV;
}

// ---------------------------------------------------------------------------
// K3: zero output (harness poisons it)
// ---------------------------------------------------------------------------
__global__ void zero_kernel(float* __restrict__ out)
{
    out[blockIdx.x * blockDim.x + threadIdx.x] = 0.0f;
}

// ---------------------------------------------------------------------------
// K4: out[b,d] = sum_t x[b,t,d] * a_t / denom[b]   (T split 32-way, atomics)
// ---------------------------------------------------------------------------
#define TSPLIT 32
__global__ __launch_bounds__(256) void wsum_kernel(
    const float* __restrict__ x, float* __restrict__ out)
{
    const int b  = blockIdx.y;
    const int t0 = blockIdx.x * (TT / TSPLIT);     // 64 tokens per block
    const int d  = threadIdx.x;

    __shared__ float asm_[TT / TSPLIT];
    for (int t = threadIdx.x; t < TT / TSPLIT; t += 256)
        asm_[t] = g_ascore[b * TT + t0 + t];
    __syncthreads();

    const float inv = 1.0f / g_denom[b];
    float acc = 0.0f;
    const float* xp = &x[((size_t)b * TT + t0) * DD + d];
    #pragma unroll 8
    for (int t = 0; t < TT / TSPLIT; t++)
        acc = fmaf(xp[(size_t)t * DD], asm_[t], acc);

    atomicAdd(&out[b * DD + d], acc * inv);
}

// ---------------------------------------------------------------------------
extern "C" void kernel_launch(void* const* d_in, const int* in_sizes, int n_in,
                              void* d_out, int out_size)
{
    const float* x    = (const float*)d_in[0];
    const float* W    = (const float*)d_in[1];
    const float* bias = (const float*)d_in[2];
    const float* uw   = (const float*)d_in[3];
    const int*   mask = (const int*)d_in[4];
    float* out = (float*)d_out;

    score_kernel<<<(BB * TT) / 64, 256>>>(x, W, bias, uw, mask);
    denom_kernel<<<BB, 256>>>();
    zero_kernel<<<(BB * DD) / 256, 256>>>(out);
    dim3 g(TSPLIT, BB);
    wsum_kernel<<<g, 256>>>(x, out);
}

// round 4
// speedup vs baseline: 5.0548x; 1.5324x over previous
#include <cuda_runtime.h>
#include <cuda_bf16.h>
#include <math.h>

#define BB 64
#define TT 2048
#define DD 256
#define EPSV 1e-7f

// Scratch (device globals — no allocations allowed)
__device__ float g_ascore[BB * TT];   // exp(score)*mask per token
__device__ float g_denom[BB];         // sum over T + EPS

// Pre-split W in MMA B-fragment order:
// [slab(8)][warp(8)][q(8)][lane(32)] uint4; q*4+c = u; u<16 -> hi frag, else lo.
// u (or u-16) = 8*kk + 2*j + r ; value = pack( split(W[2p][e]), split(W[2p+1][e]) )
// with e = warp*32 + j*8 + gid, p = slab*16 + kk*8 + tig + 4r.
__device__ uint4 g_wfrag[8][8][8][32];   // 256 KB

// pack two floats as bf16 pair (a -> low 16, b -> high 16)
__device__ __forceinline__ unsigned pack_bf16(float a, float b) {
    __nv_bfloat162 h = __floats2bfloat162_rn(a, b);
    return *reinterpret_cast<unsigned*>(&h);
}

__device__ __forceinline__ float tanh_fast(float v) {
    float y;
    asm("tanh.approx.f32 %0, %1;" : "=f"(y) : "f"(v));
    return y;
}

__device__ __forceinline__ void mma_bf16(float c[4], const unsigned a[4], const unsigned b0, const unsigned b1) {
    asm volatile(
        "mma.sync.aligned.m16n8k16.row.col.f32.bf16.bf16.f32 "
        "{%0,%1,%2,%3}, {%4,%5,%6,%7}, {%8,%9}, {%0,%1,%2,%3};\n"
        : "+f"(c[0]), "+f"(c[1]), "+f"(c[2]), "+f"(c[3])
        : "r"(a[0]), "r"(a[1]), "r"(a[2]), "r"(a[3]), "r"(b0), "r"(b1));
}

// ---------------------------------------------------------------------------
// K0: one-shot split of W into bf16 hi/lo MMA B-fragments
// ---------------------------------------------------------------------------
__global__ __launch_bounds__(256) void wsplit_kernel(const float* __restrict__ W)
{
    const int slab = blockIdx.x >> 3;
    const int warp = blockIdx.x & 7;
    const int q    = threadIdx.x >> 5;
    const int lane = threadIdx.x & 31;
    const int gid  = lane >> 2;
    const int tig  = lane & 3;

    unsigned vals[4];
    #pragma unroll
    for (int c = 0; c < 4; c++) {
        const int u  = q * 4 + c;
        const bool hi = (u < 16);
        const int f  = u & 15;
        const int kk = f >> 3;
        const int j  = (f >> 1) & 3;
        const int r  = f & 1;
        const int e  = warp * 32 + j * 8 + gid;
        const int p  = slab * 16 + kk * 8 + tig + 4 * r;
        const float w0 = W[(size_t)(2 * p) * DD + e];
        const float w1 = W[(size_t)(2 * p + 1) * DD + e];
        const float h0 = __bfloat162float(__float2bfloat16_rn(w0));
        const float h1 = __bfloat162float(__float2bfloat16_rn(w1));
        vals[c] = hi ? pack_bf16(h0, h1) : pack_bf16(w0 - h0, w1 - h1);
    }
    g_wfrag[slab][warp][q][lane] = make_uint4(vals[0], vals[1], vals[2], vals[3]);
}

// ---------------------------------------------------------------------------
// K1: fused  scores = exp( uw . tanh(x @ W + b) ) * mask   via bf16x3 MMA
// Block: 256 thr (8 warps). Tile M=64 tokens x N=256, K slab = 32, x dbl-buffered.
// B fragments come pre-split from g_wfrag (L2-resident).
// ---------------------------------------------------------------------------
__global__ __launch_bounds__(256, 2) void score_kernel(
    const float* __restrict__ x,
    const float* __restrict__ bias, const float* __restrict__ uw,
    const int* __restrict__ mask)
{
    __shared__ unsigned xs_h[2][64][17], xs_l[2][64][17];   // 17.0 KB
    __shared__ float sbias[256], suw[256];
    __shared__ float red[64][9];

    const int tid  = threadIdx.x;
    const int warp = tid >> 5;
    const int lane = tid & 31;
    const int gid  = lane >> 2;
    const int tig  = lane & 3;
    const long tile0 = (long)blockIdx.x * 64;

    sbias[tid] = bias[tid];
    suw[tid]   = uw[tid];

    // x stage mapping: this thread covers 2 float4's per slab
    const int row0 = tid >> 3;            // 0..31
    const int kq   = (tid & 7) * 4;       // 0..28
    const float* xbase0 = &x[(tile0 + row0)      * DD + kq];
    const float* xbase1 = &x[(tile0 + row0 + 32) * DD + kq];

    float acc[4][4][4];
    #pragma unroll
    for (int i = 0; i < 4; i++)
        #pragma unroll
        for (int j = 0; j < 4; j++)
            #pragma unroll
            for (int q = 0; q < 4; q++) acc[i][j][q] = 0.0f;

    // ---- prologue: stage slab 0 into buffer 0 ----
    {
        const float4 v0 = *reinterpret_cast<const float4*>(xbase0);
        const float4 v1 = *reinterpret_cast<const float4*>(xbase1);
        #pragma unroll
        for (int r = 0; r < 2; r++) {
            const float4 v = r ? v1 : v0;
            const int row = row0 + r * 32;
            const float hx = __bfloat162float(__float2bfloat16_rn(v.x));
            const float hy = __bfloat162float(__float2bfloat16_rn(v.y));
            const float hz = __bfloat162float(__float2bfloat16_rn(v.z));
            const float hw = __bfloat162float(__float2bfloat16_rn(v.w));
            xs_h[0][row][kq/2 + 0] = pack_bf16(hx, hy);
            xs_h[0][row][kq/2 + 1] = pack_bf16(hz, hw);
            xs_l[0][row][kq/2 + 0] = pack_bf16(v.x - hx, v.y - hy);
            xs_l[0][row][kq/2 + 1] = pack_bf16(v.z - hz, v.w - hw);
        }
    }
    __syncthreads();

    for (int s = 0; s < 8; s++) {
        const int buf = s & 1;

        // prefetch next x slab into registers (overlaps with MMA below)
        float4 v0, v1;
        if (s < 7) {
            v0 = *reinterpret_cast<const float4*>(xbase0 + (s + 1) * 32);
            v1 = *reinterpret_cast<const float4*>(xbase1 + (s + 1) * 32);
        }

        // ---- MMA on current slab ----
        const uint4* bp = &g_wfrag[s][warp][0][lane];
        #pragma unroll
        for (int kk = 0; kk < 2; kk++) {
            const int kb = kk * 8;
            const uint4 bhq0 = bp[(2 * kk + 0) * 32];
            const uint4 bhq1 = bp[(2 * kk + 1) * 32];
            const uint4 blq0 = bp[(2 * kk + 4) * 32];
            const uint4 blq1 = bp[(2 * kk + 5) * 32];
            const unsigned bh[8] = {bhq0.x, bhq0.y, bhq0.z, bhq0.w,
                                    bhq1.x, bhq1.y, bhq1.z, bhq1.w};
            const unsigned bl[8] = {blq0.x, blq0.y, blq0.z, blq0.w,
                                    blq1.x, blq1.y, blq1.z, blq1.w};
            #pragma unroll
            for (int i = 0; i < 4; i++) {
                const int m = i * 16;
                unsigned ah[4], al[4];
                ah[0] = xs_h[buf][m + gid    ][kb + tig];
                ah[1] = xs_h[buf][m + gid + 8][kb + tig];
                ah[2] = xs_h[buf][m + gid    ][kb + tig + 4];
                ah[3] = xs_h[buf][m + gid + 8][kb + tig + 4];
                al[0] = xs_l[buf][m + gid    ][kb + tig];
                al[1] = xs_l[buf][m + gid + 8][kb + tig];
                al[2] = xs_l[buf][m + gid    ][kb + tig + 4];
                al[3] = xs_l[buf][m + gid + 8][kb + tig + 4];
                #pragma unroll
                for (int j = 0; j < 4; j++) {
                    mma_bf16(acc[i][j], ah, bh[j * 2], bh[j * 2 + 1]);   // hi*hi
                    mma_bf16(acc[i][j], ah, bl[j * 2], bl[j * 2 + 1]);   // hi*lo
                    mma_bf16(acc[i][j], al, bh[j * 2], bh[j * 2 + 1]);   // lo*hi
                }
            }
        }

        // ---- stage prefetched slab into the other buffer ----
        if (s < 7) {
            const int nb = buf ^ 1;
            #pragma unroll
            for (int r = 0; r < 2; r++) {
                const float4 v = r ? v1 : v0;
                const int row = row0 + r * 32;
                const float hx = __bfloat162float(__float2bfloat16_rn(v.x));
                const float hy = __bfloat162float(__float2bfloat16_rn(v.y));
                const float hz = __bfloat162float(__float2bfloat16_rn(v.z));
                const float hw = __bfloat162float(__float2bfloat16_rn(v.w));
                xs_h[nb][row][kq/2 + 0] = pack_bf16(hx, hy);
                xs_h[nb][row][kq/2 + 1] = pack_bf16(hz, hw);
                xs_l[nb][row][kq/2 + 0] = pack_bf16(v.x - hx, v.y - hy);
                xs_l[nb][row][kq/2 + 1] = pack_bf16(v.z - hz, v.w - hw);
            }
            __syncthreads();
        }
    }

    // ---- epilogue: per-row  sum_e tanh(v + b[e]) * uw[e] ----
    const int n0 = warp * 32;
    #pragma unroll
    for (int i = 0; i < 4; i++) {
        float s0 = 0.0f, s1 = 0.0f;
        #pragma unroll
        for (int j = 0; j < 4; j++) {
            const int e = n0 + j * 8 + tig * 2;
            const float b0 = sbias[e], b1 = sbias[e + 1];
            const float u0 = suw[e],   u1 = suw[e + 1];
            s0 += tanh_fast(acc[i][j][0] + b0) * u0 + tanh_fast(acc[i][j][1] + b1) * u1;
            s1 += tanh_fast(acc[i][j][2] + b0) * u0 + tanh_fast(acc[i][j][3] + b1) * u1;
        }
        s0 += __shfl_xor_sync(0xffffffffu, s0, 1);
        s0 += __shfl_xor_sync(0xffffffffu, s0, 2);
        s1 += __shfl_xor_sync(0xffffffffu, s1, 1);
        s1 += __shfl_xor_sync(0xffffffffu, s1, 2);
        if (tig == 0) {
            red[i * 16 + gid    ][warp] = s0;
            red[i * 16 + gid + 8][warp] = s1;
        }
    }
    __syncthreads();

    if (tid < 64) {
        float s = 0.0f;
        #pragma unroll
        for (int w = 0; w < 8; w++) s += red[tid][w];
        const long gi = tile0 + tid;
        g_ascore[gi] = expf(s) * (float)mask[gi];
    }
}

// ---------------------------------------------------------------------------
// K2: per-batch denom = sum_t a_t + EPS
// ---------------------------------------------------------------------------
__global__ __launch_bounds__(256) void denom_kernel()
{
    __shared__ float sm[256];
    const int b = blockIdx.x;
    float s = 0.0f;
    for (int t = threadIdx.x; t < TT; t += 256) s += g_ascore[b * TT + t];
    sm[threadIdx.x] = s;
    __syncthreads();
    for (int off = 128; off > 0; off >>= 1) {
        if (threadIdx.x < off) sm[threadIdx.x] += sm[threadIdx.x + off];
        __syncthreads();
    }
    if (threadIdx.x == 0) g_denom[b] = sm[0] + EPSV;
}

// ---------------------------------------------------------------------------
// K3: zero output (harness poisons it)
// ---------------------------------------------------------------------------
__global__ void zero_kernel(float* __restrict__ out)
{
    out[blockIdx.x * blockDim.x + threadIdx.x] = 0.0f;
}

// ---------------------------------------------------------------------------
// K4: out[b,d] = sum_t x[b,t,d] * a_t / denom[b]   (T split 32-way, atomics)
// ---------------------------------------------------------------------------
#define TSPLIT 32
__global__ __launch_bounds__(256) void wsum_kernel(
    const float* __restrict__ x, float* __restrict__ out)
{
    const int b  = blockIdx.y;
    const int t0 = blockIdx.x * (TT / TSPLIT);     // 64 tokens per block
    const int d  = threadIdx.x;

    __shared__ float asm_[TT / TSPLIT];
    for (int t = threadIdx.x; t < TT / TSPLIT; t += 256)
        asm_[t] = g_ascore[b * TT + t0 + t];
    __syncthreads();

    const float inv = 1.0f / g_denom[b];
    float acc = 0.0f;
    const float* xp = &x[((size_t)b * TT + t0) * DD + d];
    #pragma unroll 8
    for (int t = 0; t < TT / TSPLIT; t++)
        acc = fmaf(xp[(size_t)t * DD], asm_[t], acc);

    atomicAdd(&out[b * DD + d], acc * inv);
}

// ---------------------------------------------------------------------------
extern "C" void kernel_launch(void* const* d_in, const int* in_sizes, int n_in,
                              void* d_out, int out_size)
{
    const float* x    = (const float*)d_in[0];
    const float* W    = (const float*)d_in[1];
    const float* bias = (const float*)d_in[2];
    const float* uw   = (const float*)d_in[3];
    const int*   mask = (const int*)d_in[4];
    float* out = (float*)d_out;

    wsplit_kernel<<<64, 256>>>(W);
    score_kernel<<<(BB * TT) / 64, 256>>>(x, bias, uw, mask);
    denom_kernel<<<BB, 256>>>();
    zero_kernel<<<(BB * DD) / 256, 256>>>(out);
    dim3 g(TSPLIT, BB);
    wsum_kernel<<<g, 256>>>(x, out);
}

// round 8
// speedup vs baseline: 10.4685x; 2.0710x over previous
#include <cuda_runtime.h>
#include <cuda_fp16.h>
#include <math.h>
#include <stdint.h>

#define BB 64
#define TT 2048
#define DD 256
#define EPSV 1e-7f

// Scratch (device globals — no allocations allowed)
__device__ float g_ascore[BB * TT];   // exp(score)*mask per token
__device__ float g_denom[BB];         // sum over T (EPS added in wsum)

// Pre-converted W (fp16) in MMA B-fragment order:
// [slab(8)][warp(8)][q(4)][lane(32)] uint4; u = q*4+c in 0..15:
// kk=u>>3, j=(u>>1)&3, r=u&1; e = warp*32 + j*8 + gid; p = slab*16 + kk*8 + tig + 4r
// value = pack_h(W[2p][e], W[2p+1][e])
__device__ uint4 g_wfrag[8][8][4][32];   // 128 KB

// smem row stride for x tiles, in 32-bit words. 20 words = 80 B = 5*16 B:
// keeps every ldmatrix row address 16B-aligned, and 80*r mod 128 covers all
// eight 16B chunks across 8 rows -> conflict-free LDSM.
#define XSTR 20

// ---------------- helpers ----------------
__device__ __forceinline__ uint32_t smem_u32(const void* p) {
    uint32_t a;
    asm("{ .reg .u64 t; cvta.to.shared.u64 t, %1; cvt.u32.u64 %0, t; }"
        : "=r"(a) : "l"(p));
    return a;
}
__device__ __forceinline__ unsigned pack_h(float a, float b) {
    __half2 h = __floats2half2_rn(a, b);
    return *reinterpret_cast<unsigned*>(&h);
}
__device__ __forceinline__ float tanh_fast(float v) {
    float y; asm("tanh.approx.f32 %0, %1;" : "=f"(y) : "f"(v)); return y;
}
__device__ __forceinline__ void mma_f16(float c[4], const unsigned a[4],
                                        const unsigned b0, const unsigned b1) {
    asm volatile(
        "mma.sync.aligned.m16n8k16.row.col.f32.f16.f16.f32 "
        "{%0,%1,%2,%3}, {%4,%5,%6,%7}, {%8,%9}, {%0,%1,%2,%3};\n"
        : "+f"(c[0]), "+f"(c[1]), "+f"(c[2]), "+f"(c[3])
        : "r"(a[0]), "r"(a[1]), "r"(a[2]), "r"(a[3]), "r"(b0), "r"(b1));
}
__device__ __forceinline__ void ldsm_x4(unsigned r[4], uint32_t addr) {
    asm volatile("ldmatrix.sync.aligned.m8n8.x4.shared.b16 {%0,%1,%2,%3}, [%4];"
                 : "=r"(r[0]), "=r"(r[1]), "=r"(r[2]), "=r"(r[3]) : "r"(addr));
}

// ---------------------------------------------------------------------------
// K0: one-shot convert of W to fp16 B-fragments; also zeroes out + g_denom.
// grid 32 x 256 = 8192 threads, one uint4 each.
// ---------------------------------------------------------------------------
__global__ __launch_bounds__(256) void wsplit_kernel(const float* __restrict__ W,
                                                     float* __restrict__ out)
{
    const int gidx = blockIdx.x * 256 + threadIdx.x;   // 0..8191
    if (gidx < BB) g_denom[gidx] = 0.0f;
    out[gidx] = 0.0f;
    out[gidx + 8192] = 0.0f;

    const int slab = gidx >> 10;
    const int rem  = gidx & 1023;
    const int wrp  = rem >> 7;
    const int q    = (rem >> 5) & 3;
    const int lane = rem & 31;
    const int gid  = lane >> 2;
    const int tig  = lane & 3;

    unsigned vals[4];
    #pragma unroll
    for (int c = 0; c < 4; c++) {
        const int u  = q * 4 + c;
        const int kk = u >> 3;
        const int j  = (u >> 1) & 3;
        const int r  = u & 1;
        const int e  = wrp * 32 + j * 8 + gid;
        const int p  = slab * 16 + kk * 8 + tig + 4 * r;
        vals[c] = pack_h(W[(size_t)(2 * p) * DD + e],
                         W[(size_t)(2 * p + 1) * DD + e]);
    }
    g_wfrag[slab][wrp][q][lane] = make_uint4(vals[0], vals[1], vals[2], vals[3]);
}

// ---------------------------------------------------------------------------
// K1: fused  scores = exp( uw . tanh(x @ W + b) ) * mask   via fp16 2-term MMA
// Block: 256 thr (8 warps). Tile M=64 tokens x N=256, K slab=32, x dbl-buffered.
// y = x_hi*W_h + x_lo*W_h  (= x*W_h exactly; error only from W fp16 rounding)
// Epilogue also accumulates the per-batch denom via one atomic per warp.
// ---------------------------------------------------------------------------
__global__ __launch_bounds__(256, 2) void score_kernel(
    const float* __restrict__ x,
    const float* __restrict__ bias, const float* __restrict__ uw,
    const int* __restrict__ mask)
{
    __shared__ __align__(16) unsigned xs_h[2][64][XSTR];   // fp16 pairs
    __shared__ __align__(16) unsigned xs_l[2][64][XSTR];
    __shared__ float sbias[256], suw[256];
    __shared__ float red[64][9];

    const int tid  = threadIdx.x;
    const int warp = tid >> 5;
    const int lane = tid & 31;
    const int gid  = lane >> 2;
    const int tig  = lane & 3;
    const long tile0 = (long)blockIdx.x * 64;

    sbias[tid] = bias[tid];
    suw[tid]   = uw[tid];

    // ldmatrix per-lane address offset: row-within-frag + k-chunk select
    const int lrow = lane & 15;                 // rows for mats 0/1
    const int lcol = (lane & 16) >> 2;          // +4 k-pair words for mats 2/3
    const uint32_t uh_base = smem_u32(&xs_h[0][0][0]);
    const uint32_t ul_base = smem_u32(&xs_l[0][0][0]);
    const uint32_t lofs = (uint32_t)(lrow * XSTR + lcol) * 4u;

    // x stage mapping: this thread covers 2 float4's per slab
    const int row0 = tid >> 3;            // 0..31
    const int kq   = (tid & 7) * 4;       // 0..28
    const float* xbase0 = &x[(tile0 + row0)      * DD + kq];
    const float* xbase1 = &x[(tile0 + row0 + 32) * DD + kq];

    float acc[4][4][4];
    #pragma unroll
    for (int i = 0; i < 4; i++)
        #pragma unroll
        for (int j = 0; j < 4; j++)
            #pragma unroll
            for (int q = 0; q < 4; q++) acc[i][j][q] = 0.0f;

    // ---- prologue: stage slab 0 into buffer 0 ----
    {
        const float4 v0 = *reinterpret_cast<const float4*>(xbase0);
        const float4 v1 = *reinterpret_cast<const float4*>(xbase1);
        #pragma unroll
        for (int r = 0; r < 2; r++) {
            const float4 v = r ? v1 : v0;
            const int row = row0 + r * 32;
            const float hx = __half2float(__float2half_rn(v.x));
            const float hy = __half2float(__float2half_rn(v.y));
            const float hz = __half2float(__float2half_rn(v.z));
            const float hw = __half2float(__float2half_rn(v.w));
            xs_h[0][row][kq/2 + 0] = pack_h(hx, hy);
            xs_h[0][row][kq/2 + 1] = pack_h(hz, hw);
            xs_l[0][row][kq/2 + 0] = pack_h(v.x - hx, v.y - hy);
            xs_l[0][row][kq/2 + 1] = pack_h(v.z - hz, v.w - hw);
        }
    }
    __syncthreads();

    for (int s = 0; s < 8; s++) {
        const int buf = s & 1;

        // prefetch B fragments for this slab (L2-resident)
        const uint4* bp = &g_wfrag[s][warp][0][lane];
        uint4 bq0 = bp[0];
        uint4 bq1 = bp[32];
        uint4 bq2 = bp[64];
        uint4 bq3 = bp[96];

        // prefetch next x slab into registers (overlaps with MMA below)
        float4 v0, v1;
        if (s < 7) {
            v0 = *reinterpret_cast<const float4*>(xbase0 + (s + 1) * 32);
            v1 = *reinterpret_cast<const float4*>(xbase1 + (s + 1) * 32);
        }

        // ---- MMA on current slab: 2 kk x 4 i x 4 j x 2 terms = 64 HMMA ----
        const uint32_t abase = (uint32_t)(buf * 64 * XSTR) * 4u;
        #pragma unroll
        for (int kk = 0; kk < 2; kk++) {
            const uint4 qa = kk ? bq2 : bq0;
            const uint4 qb = kk ? bq3 : bq1;
            const unsigned b[8] = {qa.x, qa.y, qa.z, qa.w, qb.x, qb.y, qb.z, qb.w};
            #pragma unroll
            for (int i = 0; i < 4; i++) {
                const uint32_t fo = abase + (uint32_t)(i * 16 * XSTR + kk * 8) * 4u + lofs;
                unsigned ah[4], al[4];
                ldsm_x4(ah, uh_base + fo);
                ldsm_x4(al, ul_base + fo);
                #pragma unroll
                for (int j = 0; j < 4; j++) {
                    mma_f16(acc[i][j], ah, b[j * 2], b[j * 2 + 1]);   // x_hi * W
                    mma_f16(acc[i][j], al, b[j * 2], b[j * 2 + 1]);   // x_lo * W
                }
            }
        }

        // ---- stage prefetched slab into the other buffer ----
        if (s < 7) {
            const int nb = buf ^ 1;
            #pragma unroll
            for (int r = 0; r < 2; r++) {
                const float4 v = r ? v1 : v0;
                const int row = row0 + r * 32;
                const float hx = __half2float(__float2half_rn(v.x));
                const float hy = __half2float(__float2half_rn(v.y));
                const float hz = __half2float(__float2half_rn(v.z));
                const float hw = __half2float(__float2half_rn(v.w));
                xs_h[nb][row][kq/2 + 0] = pack_h(hx, hy);
                xs_h[nb][row][kq/2 + 1] = pack_h(hz, hw);
                xs_l[nb][row][kq/2 + 0] = pack_h(v.x - hx, v.y - hy);
                xs_l[nb][row][kq/2 + 1] = pack_h(v.z - hz, v.w - hw);
            }
            __syncthreads();
        }
    }

    // ---- epilogue: per-row  sum_e tanh(v + b[e]) * uw[e] ----
    const int n0 = warp * 32;
    #pragma unroll
    for (int i = 0; i < 4; i++) {
        float s0 = 0.0f, s1 = 0.0f;
        #pragma unroll
        for (int j = 0; j < 4; j++) {
            const int e = n0 + j * 8 + tig * 2;
            const float b0 = sbias[e], b1 = sbias[e + 1];
            const float u0 = suw[e],   u1 = suw[e + 1];
            s0 += tanh_fast(acc[i][j][0] + b0) * u0 + tanh_fast(acc[i][j][1] + b1) * u1;
            s1 += tanh_fast(acc[i][j][2] + b0) * u0 + tanh_fast(acc[i][j][3] + b1) * u1;
        }
        s0 += __shfl_xor_sync(0xffffffffu, s0, 1);
        s0 += __shfl_xor_sync(0xffffffffu, s0, 2);
        s1 += __shfl_xor_sync(0xffffffffu, s1, 1);
        s1 += __shfl_xor_sync(0xffffffffu, s1, 2);
        if (tig == 0) {
            red[i * 16 + gid    ][warp] = s0;
            red[i * 16 + gid + 8][warp] = s1;
        }
    }
    __syncthreads();

    if (tid < 64) {
        float s = 0.0f;
        #pragma unroll
        for (int w = 0; w < 8; w++) s += red[tid][w];
        const long gi = tile0 + tid;
        const float a = expf(s) * (float)mask[gi];
        g_ascore[gi] = a;
        // per-batch denom partial: 32 blocks per batch (blockIdx.x >> 5)
        float ws = a;
        #pragma unroll
        for (int off = 16; off; off >>= 1)
            ws += __shfl_xor_sync(0xffffffffu, ws, off);
        if (lane == 0) atomicAdd(&g_denom[blockIdx.x >> 5], ws);
    }
}

// ---------------------------------------------------------------------------
// K2: out[b,d] = sum_t x[b,t,d] * a_t / (denom[b]+EPS)  (T split 32-way)
// ---------------------------------------------------------------------------
#define TSPLIT 32
__global__ __launch_bounds__(256) void wsum_kernel(
    const float* __restrict__ x, float* __restrict__ out)
{
    const int b  = blockIdx.y;
    const int t0 = blockIdx.x * (TT / TSPLIT);     // 64 tokens per block
    const int d  = threadIdx.x;

    __shared__ float asm_[TT / TSPLIT];
    for (int t = threadIdx.x; t < TT / TSPLIT; t += 256)
        asm_[t] = g_ascore[b * TT + t0 + t];
    __syncthreads();

    const float inv = 1.0f / (g_denom[b] + EPSV);
    float acc = 0.0f;
    const float* xp = &x[((size_t)b * TT + t0) * DD + d];
    #pragma unroll 8
    for (int t = 0; t < TT / TSPLIT; t++)
        acc = fmaf(xp[(size_t)t * DD], asm_[t], acc);

    atomicAdd(&out[b * DD + d], acc * inv);
}

// ---------------------------------------------------------------------------
extern "C" void kernel_launch(void* const* d_in, const int* in_sizes, int n_in,
                              void* d_out, int out_size)
{
    const float* x    = (const float*)d_in[0];
    const float* W    = (const float*)d_in[1];
    const float* bias = (const float*)d_in[2];
    const float* uw   = (const float*)d_in[3];
    const int*   mask = (const int*)d_in[4];
    float* out = (float*)d_out;

    wsplit_kernel<<<32, 256>>>(W, out);
    score_kernel<<<(BB * TT) / 64, 256>>>(x, bias, uw, mask);
    dim3 g(TSPLIT, BB);
    wsum_kernel<<<g, 256>>>(x, out);
}

// round 9
// speedup vs baseline: 14.5389x; 1.3888x over previous
#include <cuda_runtime.h>
#include <cuda_fp16.h>
#include <math.h>
#include <stdint.h>

#define BB 64
#define TT 2048
#define DD 256
#define EPSV 1e-7f

// Scratch (device globals — no allocations allowed)
__device__ float g_denom[BB];         // sum over T (EPS added in norm)

// Pre-converted W (fp16) in MMA B-fragment order:
// [slab(8)][warp(8)][q(4)][lane(32)] uint4; u = q*4+c in 0..15:
// kk=u>>3, j=(u>>1)&3, r=u&1; e = warp*32 + j*8 + gid; p = slab*16 + kk*8 + tig + 4r
// value = pack_h(W[2p][e], W[2p+1][e])
__device__ uint4 g_wfrag[8][8][4][32];   // 128 KB

// smem row stride for the x tile, in 32-bit words. 132 words = 528 B = 33*16:
// every ldmatrix row address stays 16B-aligned, and 528 mod 128 = 16 so the
// 8 rows of each 8x8 matrix land on distinct 128B phases -> conflict-free LDSM.
#define XSTR 132

// ---------------- helpers ----------------
__device__ __forceinline__ uint32_t smem_u32(const void* p) {
    uint32_t a;
    asm("{ .reg .u64 t; cvta.to.shared.u64 t, %1; cvt.u32.u64 %0, t; }"
        : "=r"(a) : "l"(p));
    return a;
}
__device__ __forceinline__ unsigned pack_h(float a, float b) {
    __half2 h = __floats2half2_rn(a, b);
    return *reinterpret_cast<unsigned*>(&h);
}
__device__ __forceinline__ float tanh_fast(float v) {
    float y; asm("tanh.approx.f32 %0, %1;" : "=f"(y) : "f"(v)); return y;
}
__device__ __forceinline__ void mma_f16(float c[4], const unsigned a[4],
                                        const unsigned b0, const unsigned b1) {
    asm volatile(
        "mma.sync.aligned.m16n8k16.row.col.f32.f16.f16.f32 "
        "{%0,%1,%2,%3}, {%4,%5,%6,%7}, {%8,%9}, {%0,%1,%2,%3};\n"
        : "+f"(c[0]), "+f"(c[1]), "+f"(c[2]), "+f"(c[3])
        : "r"(a[0]), "r"(a[1]), "r"(a[2]), "r"(a[3]), "r"(b0), "r"(b1));
}
__device__ __forceinline__ void ldsm_x4(unsigned r[4], uint32_t addr) {
    asm volatile("ldmatrix.sync.aligned.m8n8.x4.shared.b16 {%0,%1,%2,%3}, [%4];"
                 : "=r"(r[0]), "=r"(r[1]), "=r"(r[2]), "=r"(r[3]) : "r"(addr));
}

// ---------------------------------------------------------------------------
// K0: one-shot convert of W to fp16 B-fragments; also zeroes out + g_denom.
// grid 32 x 256 = 8192 threads, one uint4 each.
// ---------------------------------------------------------------------------
__global__ __launch_bounds__(256) void wsplit_kernel(const float* __restrict__ W,
                                                     float* __restrict__ out)
{
    const int gidx = blockIdx.x * 256 + threadIdx.x;   // 0..8191
    if (gidx < BB) g_denom[gidx] = 0.0f;
    out[gidx] = 0.0f;
    out[gidx + 8192] = 0.0f;

    const int slab = gidx >> 10;
    const int rem  = gidx & 1023;
    const int wrp  = rem >> 7;
    const int q    = (rem >> 5) & 3;
    const int lane = rem & 31;
    const int gid  = lane >> 2;
    const int tig  = lane & 3;

    unsigned vals[4];
    #pragma unroll
    for (int c = 0; c < 4; c++) {
        const int u  = q * 4 + c;
        const int kk = u >> 3;
        const int j  = (u >> 1) & 3;
        const int r  = u & 1;
        const int e  = wrp * 32 + j * 8 + gid;
        const int p  = slab * 16 + kk * 8 + tig + 4 * r;
        vals[c] = pack_h(W[(size_t)(2 * p) * DD + e],
                         W[(size_t)(2 * p + 1) * DD + e]);
    }
    g_wfrag[slab][wrp][q][lane] = make_uint4(vals[0], vals[1], vals[2], vals[3]);
}

// ---------------------------------------------------------------------------
// K1: fused  a = exp( uw . tanh(x @ W + b) ) * mask   AND the weighted sum:
// atomically accumulates  out[b,d] += sum_t a_t * x[t,d]   (numerator) and
// g_denom[b] += sum_t a_t.  Single fp16 MMA pass (x and W both fp16).
// Block: 256 thr (8 warps). Tile M=64 tokens x N=256, full K=256 in smem.
// ---------------------------------------------------------------------------
__global__ __launch_bounds__(256, 2) void score_kernel(
    const float* __restrict__ x,
    const float* __restrict__ bias, const float* __restrict__ uw,
    const int* __restrict__ mask, float* __restrict__ out)
{
    __shared__ __align__(16) unsigned xs[64][XSTR];   // fp16 pairs, 33.8 KB
    __shared__ float sbias[256], suw[256];
    __shared__ float red[64][9];
    __shared__ float sa[64];

    const int tid  = threadIdx.x;
    const int warp = tid >> 5;
    const int lane = tid & 31;
    const int gid  = lane >> 2;
    const int tig  = lane & 3;
    const long tile0 = (long)blockIdx.x * 64;
    const int  batch = blockIdx.x >> 5;    // 32 blocks per batch

    sbias[tid] = bias[tid];
    suw[tid]   = uw[tid];

    // ldmatrix per-lane address offset
    const int lrow = lane & 15;
    const int lcol = (lane & 16) >> 2;          // +4 words for mats 2/3
    const uint32_t xs_base = smem_u32(&xs[0][0]);
    const uint32_t lofs = (uint32_t)(lrow * XSTR + lcol) * 4u;

    // ---- stage the full 64x256 x tile as fp16 pairs (16 float4 / thread) ----
    #pragma unroll
    for (int q = 0; q < 16; q++) {
        const int idx = q * 256 + tid;
        const int row = idx >> 6;
        const int c4  = idx & 63;
        const float4 v = *reinterpret_cast<const float4*>(
            &x[(tile0 + row) * DD + c4 * 4]);
        uint2 p;
        p.x = pack_h(v.x, v.y);
        p.y = pack_h(v.z, v.w);
        *reinterpret_cast<uint2*>(&xs[row][c4 * 2]) = p;
    }
    __syncthreads();

    float acc[4][4][4];
    #pragma unroll
    for (int i = 0; i < 4; i++)
        #pragma unroll
        for (int j = 0; j < 4; j++)
            #pragma unroll
            for (int q = 0; q < 4; q++) acc[i][j][q] = 0.0f;

    // ---- MMA: 8 slabs x 2 kk x 4 i x 4 j = 256 HMMA per warp ----
    #pragma unroll
    for (int s = 0; s < 8; s++) {
        const uint4* bp = &g_wfrag[s][warp][0][lane];
        const uint4 bq0 = bp[0];
        const uint4 bq1 = bp[32];
        const uint4 bq2 = bp[64];
        const uint4 bq3 = bp[96];
        #pragma unroll
        for (int kk = 0; kk < 2; kk++) {
            const uint4 qa = kk ? bq2 : bq0;
            const uint4 qb = kk ? bq3 : bq1;
            const unsigned b[8] = {qa.x, qa.y, qa.z, qa.w, qb.x, qb.y, qb.z, qb.w};
            #pragma unroll
            for (int i = 0; i < 4; i++) {
                const uint32_t fo = (uint32_t)(i * 16 * XSTR + s * 16 + kk * 8) * 4u + lofs;
                unsigned ah[4];
                ldsm_x4(ah, xs_base + fo);
                #pragma unroll
                for (int j = 0; j < 4; j++)
                    mma_f16(acc[i][j], ah, b[j * 2], b[j * 2 + 1]);
            }
        }
    }

    // ---- epilogue: per-row  sum_e tanh(v + b[e]) * uw[e] ----
    const int n0 = warp * 32;
    #pragma unroll
    for (int i = 0; i < 4; i++) {
        float s0 = 0.0f, s1 = 0.0f;
        #pragma unroll
        for (int j = 0; j < 4; j++) {
            const int e = n0 + j * 8 + tig * 2;
            const float b0 = sbias[e], b1 = sbias[e + 1];
            const float u0 = suw[e],   u1 = suw[e + 1];
            s0 += tanh_fast(acc[i][j][0] + b0) * u0 + tanh_fast(acc[i][j][1] + b1) * u1;
            s1 += tanh_fast(acc[i][j][2] + b0) * u0 + tanh_fast(acc[i][j][3] + b1) * u1;
        }
        s0 += __shfl_xor_sync(0xffffffffu, s0, 1);
        s0 += __shfl_xor_sync(0xffffffffu, s0, 2);
        s1 += __shfl_xor_sync(0xffffffffu, s1, 1);
        s1 += __shfl_xor_sync(0xffffffffu, s1, 2);
        if (tig == 0) {
            red[i * 16 + gid    ][warp] = s0;
            red[i * 16 + gid + 8][warp] = s1;
        }
    }
    __syncthreads();

    if (tid < 64) {
        float s = 0.0f;
        #pragma unroll
        for (int w = 0; w < 8; w++) s += red[tid][w];
        const long gi = tile0 + tid;
        const float a = expf(s) * (float)mask[gi];
        sa[tid] = a;
        float ws = a;
        #pragma unroll
        for (int off = 16; off; off >>= 1)
            ws += __shfl_xor_sync(0xffffffffu, ws, off);
        if (lane == 0) atomicAdd(&g_denom[batch], ws);
    }
    __syncthreads();

    // ---- fused weighted sum: out[b, dq..dq+3] += sum_t a_t * x[t, dq..dq+3]
    // thread covers one d-quad for 16 of the 64 tokens; x tile is L2-hot.
    {
        const int dq = (tid & 63) * 4;
        const int tg = tid >> 6;               // t-group 0..3
        const float* xp = &x[(tile0 + tg * 16) * DD + dq];
        float4 a4 = make_float4(0.f, 0.f, 0.f, 0.f);
        #pragma unroll
        for (int t = 0; t < 16; t++) {
            const float4 v = *reinterpret_cast<const float4*>(xp + (size_t)t * DD);
            const float w = sa[tg * 16 + t];
            a4.x = fmaf(v.x, w, a4.x);
            a4.y = fmaf(v.y, w, a4.y);
            a4.z = fmaf(v.z, w, a4.z);
            a4.w = fmaf(v.w, w, a4.w);
        }
        float* op = &out[batch * DD + dq];
        atomicAdd(op + 0, a4.x);
        atomicAdd(op + 1, a4.y);
        atomicAdd(op + 2, a4.z);
        atomicAdd(op + 3, a4.w);
    }
}

// ---------------------------------------------------------------------------
// K2: out[b,d] /= (denom[b] + EPS)
// ---------------------------------------------------------------------------
__global__ __launch_bounds__(256) void norm_kernel(float* __restrict__ out)
{
    const int b = blockIdx.x;
    out[b * DD + threadIdx.x] *= 1.0f / (g_denom[b] + EPSV);
}

// ---------------------------------------------------------------------------
extern "C" void kernel_launch(void* const* d_in, const int* in_sizes, int n_in,
                              void* d_out, int out_size)
{
    const float* x    = (const float*)d_in[0];
    const float* W    = (const float*)d_in[1];
    const float* bias = (const float*)d_in[2];
    const float* uw   = (const float*)d_in[3];
    const int*   mask = (const int*)d_in[4];
    float* out = (float*)d_out;

    wsplit_kernel<<<32, 256>>>(W, out);
    score_kernel<<<(BB * TT) / 64, 256>>>(x, bias, uw, mask, out);
    norm_kernel<<<BB, 256>>>(out);
}